// round 1
// baseline (speedup 1.0000x reference)
#include <cuda_runtime.h>
#include <cstdint>
#include <cstddef>

// Problem dims (fixed for this problem instance)
#define BD 4096   // batch
#define ID 2048   // in features
#define FD 4096   // out features

// ---------------------------------------------------------------------------
// Scratch (device globals; no dynamic allocation allowed)
// ---------------------------------------------------------------------------
__device__ float       g_xbuf[(size_t)BD * ID];   // 32 MB : rotated activations
__device__ float       g_wbuf[(size_t)ID * FD];   // 32 MB : rotated weights
__device__ float       g_zbuf[(size_t)BD * FD];   // 64 MB : post-GEMM rotation staging
__device__ int         g_acc [(size_t)BD * FD];   // 64 MB : int32 GEMM accumulators
__device__ signed char g_qx  [(size_t)BD * ID];   //  8 MB : int8 activations [M,K]
__device__ signed char g_qwT [(size_t)FD * ID];   //  8 MB : int8 weights transposed [N,K]
__device__ unsigned    g_maxbits[2];              // |xr|max bits, |wr|max bits

// ---------------------------------------------------------------------------
__global__ void zero_max_kernel(unsigned* m) {
    if (threadIdx.x < 2) m[threadIdx.x] = 0u;
}

// ---------------------------------------------------------------------------
// Radix-64 FWHT pass along dim0 of a [4096, ncols] matrix.
// H_4096 = H_64 (outer index bo) ⊗ H_64 (inner index bi), b = 64*bo + bi.
// Pass selects rows: row(j) = g*gMul + j*jStep, j in [0,64), g = blockIdx.y.
//   inner pass: gMul=64, jStep=1 ; outer pass: gMul=1, jStep=64
// Optional: scalebits != null -> scale *= (sx/127)*(sw/127) read from device
//           maxbits   != null -> atomicMax of |out|
//           bias      != null -> add bias[col]
// ---------------------------------------------------------------------------
__global__ void fwht64_pass(const float* __restrict__ in, float* __restrict__ out,
                            int ncols, int gMul, int jStep, float scale,
                            const unsigned* __restrict__ scalebits,
                            unsigned* __restrict__ maxbits,
                            const float* __restrict__ bias)
{
    __shared__ float tile[64][65];
    __shared__ float red[256];

    const int ct  = blockIdx.x;
    const int g   = blockIdx.y;
    const int c0  = ct * 64;
    const int rb  = g * gMul;
    const int tid = threadIdx.x;

    #pragma unroll
    for (int idx = tid; idx < 4096; idx += 256) {
        int j = idx >> 6, c = idx & 63;
        tile[j][c] = in[(size_t)(rb + j * jStep) * ncols + c0 + c];
    }
    __syncthreads();

    #pragma unroll
    for (int st = 0; st < 6; ++st) {
        const int h = 1 << st;
        for (int p = tid; p < 2048; p += 256) {
            int c = p & 63, t = p >> 6;
            int i = ((t >> st) << (st + 1)) + (t & (h - 1));
            float a = tile[i][c], b = tile[i + h][c];
            tile[i][c]     = a + b;
            tile[i + h][c] = a - b;
        }
        __syncthreads();
    }

    float sc = scale;
    if (scalebits) {
        float sx = __uint_as_float(scalebits[0]) / 127.0f;
        float sw = __uint_as_float(scalebits[1]) / 127.0f;
        sc *= sx * sw;
    }

    float lmax = 0.0f;
    #pragma unroll
    for (int idx = tid; idx < 4096; idx += 256) {
        int j = idx >> 6, c = idx & 63;
        float v = tile[j][c] * sc;
        if (bias) v += bias[c0 + c];
        out[(size_t)(rb + j * jStep) * ncols + c0 + c] = v;
        lmax = fmaxf(lmax, fabsf(v));
    }

    if (maxbits) {
        red[tid] = lmax;
        __syncthreads();
        for (int s = 128; s > 0; s >>= 1) {
            if (tid < s) red[tid] = fmaxf(red[tid], red[tid + s]);
            __syncthreads();
        }
        if (tid == 0) atomicMax(maxbits, __float_as_uint(red[0]));
    }
}

// ---------------------------------------------------------------------------
// Full 4096-pt FWHT along contiguous rows (float input), scale + optional max.
// One CTA per row, 1024 threads, 16 KB smem.
// ---------------------------------------------------------------------------
__global__ void fwht_rows_f32(const float* __restrict__ in, float* __restrict__ out,
                              float scale, unsigned* __restrict__ maxbits)
{
    __shared__ float s[4096];
    const int row = blockIdx.x;
    const int tid = threadIdx.x;
    const float* rp = in + (size_t)row * 4096;

    for (int i = tid; i < 4096; i += 1024) s[i] = rp[i];
    __syncthreads();

    #pragma unroll
    for (int st = 0; st < 12; ++st) {
        const int h = 1 << st;
        #pragma unroll
        for (int pp = 0; pp < 2; ++pp) {
            int p = tid + pp * 1024;
            int i = ((p >> st) << (st + 1)) + (p & (h - 1));
            float a = s[i], b = s[i + h];
            s[i]     = a + b;
            s[i + h] = a - b;
        }
        __syncthreads();
    }

    float lmax = 0.0f;
    float* op = out + (size_t)row * 4096;
    for (int i = tid; i < 4096; i += 1024) {
        float v = s[i] * scale;
        op[i] = v;
        lmax = fmaxf(lmax, fabsf(v));
    }

    if (maxbits) {
        __syncthreads();
        s[tid] = lmax;
        __syncthreads();
        for (int st = 512; st > 0; st >>= 1) {
            if (tid < st) s[tid] = fmaxf(s[tid], s[tid + st]);
            __syncthreads();
        }
        if (tid == 0) atomicMax(maxbits, __float_as_uint(s[0]));
    }
}

// Same transform but int32 input (GEMM accumulators), no scale/max.
__global__ void fwht_rows_i32(const int* __restrict__ in, float* __restrict__ out)
{
    __shared__ float s[4096];
    const int row = blockIdx.x;
    const int tid = threadIdx.x;
    const int* rp = in + (size_t)row * 4096;

    for (int i = tid; i < 4096; i += 1024) s[i] = (float)rp[i];
    __syncthreads();

    #pragma unroll
    for (int st = 0; st < 12; ++st) {
        const int h = 1 << st;
        #pragma unroll
        for (int pp = 0; pp < 2; ++pp) {
            int p = tid + pp * 1024;
            int i = ((p >> st) << (st + 1)) + (p & (h - 1));
            float a = s[i], b = s[i + h];
            s[i]     = a + b;
            s[i + h] = a - b;
        }
        __syncthreads();
    }

    float* op = out + (size_t)row * 4096;
    for (int i = tid; i < 4096; i += 1024) op[i] = s[i];
}

// ---------------------------------------------------------------------------
// Stochastic quantization, elementwise (x path): q = floor(v/s) + (noise<frac),
// clipped to [-127,127]. Matches reference float ops exactly.
// ---------------------------------------------------------------------------
__global__ void quant_kernel(const float* __restrict__ v, const float* __restrict__ noise,
                             signed char* __restrict__ q,
                             const unsigned* __restrict__ maxbits, size_t n)
{
    const float s = __uint_as_float(*maxbits) / 127.0f;
    const size_t stride = (size_t)gridDim.x * blockDim.x;
    for (size_t i = (size_t)blockIdx.x * blockDim.x + threadIdx.x; i < n; i += stride) {
        float xs = v[i] / s;
        float f  = floorf(xs);
        float qv = f + ((noise[i] < xs - f) ? 1.0f : 0.0f);
        qv = fminf(fmaxf(qv, -127.0f), 127.0f);
        q[i] = (signed char)(int)qv;
    }
}

// Quantize w and store TRANSPOSED: wr [K=2048, N=4096] -> qT [N=4096, K=2048].
// 64x64 tiles through smem (pitch 68 bytes -> conflict-free byte writes).
__global__ void quant_w_T_kernel(const float* __restrict__ wr, const float* __restrict__ noise,
                                 signed char* __restrict__ qT,
                                 const unsigned* __restrict__ maxbits)
{
    __shared__ signed char t[64][68];
    const float s = __uint_as_float(*maxbits) / 127.0f;
    const int k0 = blockIdx.x * 64;   // K tiles: 2048/64 = 32
    const int n0 = blockIdx.y * 64;   // N tiles: 4096/64 = 64
    const int tid = threadIdx.x;      // 256 threads

    #pragma unroll
    for (int idx = tid; idx < 4096; idx += 256) {
        int kl = idx >> 6, nl = idx & 63;
        size_t gi = (size_t)(k0 + kl) * FD + (n0 + nl);
        float xs = wr[gi] / s;
        float f  = floorf(xs);
        float qv = f + ((noise[gi] < xs - f) ? 1.0f : 0.0f);
        qv = fminf(fmaxf(qv, -127.0f), 127.0f);
        t[nl][kl] = (signed char)(int)qv;
    }
    __syncthreads();

    #pragma unroll
    for (int idx = tid; idx < 1024; idx += 256) {
        int nl = idx >> 4, k4 = (idx & 15) * 4;
        char4 v = make_char4(t[nl][k4], t[nl][k4 + 1], t[nl][k4 + 2], t[nl][k4 + 3]);
        *(char4*)&qT[(size_t)(n0 + nl) * ID + k0 + k4] = v;
    }
}

// ---------------------------------------------------------------------------
// int8 GEMM: C[M=4096, N=4096] (int32) = A[M, K=2048] * B[N, K]^T
// A = g_qx (row-major, K contig), B = g_qwT (row-major by N, K contig).
// CTA tile 128x128, K-step 64, double-buffered cp.async, 8 warps (64x32 each),
// mma.sync.aligned.m16n8k32.row.col.s32.s8.s8.s32.
// ---------------------------------------------------------------------------
__device__ __forceinline__ void cp16(unsigned smem, const void* gmem) {
    asm volatile("cp.async.cg.shared.global [%0], [%1], 16;" :: "r"(smem), "l"(gmem));
}

__global__ __launch_bounds__(256, 2)
void gemm_s8_kernel(const signed char* __restrict__ A,
                    const signed char* __restrict__ B,
                    int* __restrict__ C)
{
    __shared__ __align__(16) signed char As[2][128 * 64];
    __shared__ __align__(16) signed char Bs[2][128 * 64];

    const int m0 = blockIdx.y * 128;
    const int n0 = blockIdx.x * 128;
    const int tid  = threadIdx.x;
    const int lane = tid & 31;
    const int warp = tid >> 5;
    const int wm = warp & 1;   // 0..1  -> 64-row slab
    const int wn = warp >> 1;  // 0..3  -> 32-col slab

    // loader: 256 threads, each thread 2 rows x 16B for A and B
    const int lr = tid >> 2;          // 0..63
    const int lk = (tid & 3) * 16;    // 0,16,32,48

    int c[4][4][4];
    #pragma unroll
    for (int i = 0; i < 4; ++i)
        #pragma unroll
        for (int j = 0; j < 4; ++j)
            #pragma unroll
            for (int k = 0; k < 4; ++k) c[i][j][k] = 0;

    auto load_tile = [&](int buf, int k0) {
        const signed char* ga = A + (size_t)(m0 + lr) * ID + k0 + lk;
        const signed char* gb = B + (size_t)(n0 + lr) * ID + k0 + lk;
        unsigned sa = (unsigned)__cvta_generic_to_shared(&As[buf][lr * 64 + lk]);
        unsigned sb = (unsigned)__cvta_generic_to_shared(&Bs[buf][lr * 64 + lk]);
        cp16(sa, ga);
        cp16(sb, gb);
        cp16(sa + 64 * 64, ga + (size_t)64 * ID);
        cp16(sb + 64 * 64, gb + (size_t)64 * ID);
    };

    load_tile(0, 0);
    asm volatile("cp.async.commit_group;");

    const int KT = ID / 64;  // 32
    for (int kt = 0; kt < KT; ++kt) {
        if (kt + 1 < KT) {
            load_tile((kt + 1) & 1, (kt + 1) * 64);
            asm volatile("cp.async.commit_group;");
            asm volatile("cp.async.wait_group 1;");
        } else {
            asm volatile("cp.async.wait_group 0;");
        }
        __syncthreads();

        const signed char* as = As[kt & 1];
        const signed char* bs = Bs[kt & 1];

        #pragma unroll
        for (int h = 0; h < 2; ++h) {
            const int kk = h * 32 + (lane & 3) * 4;
            int a[4][4], b[4][2];
            #pragma unroll
            for (int mi = 0; mi < 4; ++mi) {
                int r = wm * 64 + mi * 16 + (lane >> 2);
                a[mi][0] = *(const int*)(as + r * 64 + kk);
                a[mi][1] = *(const int*)(as + (r + 8) * 64 + kk);
                a[mi][2] = *(const int*)(as + r * 64 + kk + 16);
                a[mi][3] = *(const int*)(as + (r + 8) * 64 + kk + 16);
            }
            #pragma unroll
            for (int ni = 0; ni < 4; ++ni) {
                int cn = wn * 32 + ni * 8 + (lane >> 2);
                b[ni][0] = *(const int*)(bs + cn * 64 + kk);
                b[ni][1] = *(const int*)(bs + cn * 64 + kk + 16);
            }
            #pragma unroll
            for (int mi = 0; mi < 4; ++mi)
                #pragma unroll
                for (int ni = 0; ni < 4; ++ni)
                    asm volatile(
                        "mma.sync.aligned.m16n8k32.row.col.s32.s8.s8.s32 "
                        "{%0,%1,%2,%3},{%4,%5,%6,%7},{%8,%9},{%0,%1,%2,%3};"
                        : "+r"(c[mi][ni][0]), "+r"(c[mi][ni][1]),
                          "+r"(c[mi][ni][2]), "+r"(c[mi][ni][3])
                        : "r"(a[mi][0]), "r"(a[mi][1]), "r"(a[mi][2]), "r"(a[mi][3]),
                          "r"(b[ni][0]), "r"(b[ni][1]));
        }
        __syncthreads();
    }

    // epilogue: int32 accumulators to gmem
    #pragma unroll
    for (int mi = 0; mi < 4; ++mi) {
        #pragma unroll
        for (int ni = 0; ni < 4; ++ni) {
            int row = m0 + wm * 64 + mi * 16 + (lane >> 2);
            int col = n0 + wn * 32 + ni * 8 + (lane & 3) * 2;
            *(int2*)&C[(size_t)row * FD + col]       = make_int2(c[mi][ni][0], c[mi][ni][1]);
            *(int2*)&C[(size_t)(row + 8) * FD + col] = make_int2(c[mi][ni][2], c[mi][ni][3]);
        }
    }
}

// ---------------------------------------------------------------------------
extern "C" void kernel_launch(void* const* d_in, const int* in_sizes, int n_in,
                              void* d_out, int out_size)
{
    const float* x    = (const float*)d_in[0];  // [4096, 2048]
    const float* w    = (const float*)d_in[1];  // [2048, 4096]
    const float* bias = (const float*)d_in[2];  // [4096]
    // d_in[3] = h1, d_in[4] = h2 : not needed (FWHT)
    const float* nx   = (const float*)d_in[5];  // [4096, 2048]
    const float* nw   = (const float*)d_in[6];  // [2048, 4096]
    float* out = (float*)d_out;                 // [4096, 4096]

    float *xbuf, *wbuf, *zbuf;
    int* acc;
    signed char *qx, *qwT;
    unsigned* mx;
    cudaGetSymbolAddress((void**)&xbuf, g_xbuf);
    cudaGetSymbolAddress((void**)&wbuf, g_wbuf);
    cudaGetSymbolAddress((void**)&zbuf, g_zbuf);
    cudaGetSymbolAddress((void**)&acc,  g_acc);
    cudaGetSymbolAddress((void**)&qx,   g_qx);
    cudaGetSymbolAddress((void**)&qwT,  g_qwT);
    cudaGetSymbolAddress((void**)&mx,   g_maxbits);

    zero_max_kernel<<<1, 32>>>(mx);

    // xr = FWHT_batch(x)/64 ; max|xr| -> mx[0]
    fwht64_pass<<<dim3(ID / 64, 64), 256>>>(x,    xbuf, ID, 64, 1,  1.0f,        nullptr, nullptr, nullptr);
    fwht64_pass<<<dim3(ID / 64, 64), 256>>>(xbuf, xbuf, ID, 1,  64, 1.0f / 64.0f, nullptr, mx + 0,  nullptr);

    // wr = FWHT_feat(w)/64 ; max|wr| -> mx[1]
    fwht_rows_f32<<<ID, 1024>>>(w, wbuf, 1.0f / 64.0f, mx + 1);

    // stochastic int8 quantization
    quant_kernel<<<2048, 256>>>(xbuf, nx, qx, mx + 0, (size_t)BD * ID);
    quant_w_T_kernel<<<dim3(ID / 64, FD / 64), 256>>>(wbuf, nw, qwT, mx + 1);

    // exact int8 GEMM: acc = qx @ qwT^T
    gemm_s8_kernel<<<dim3(FD / 128, BD / 128), 256>>>(qx, qwT, acc);

    // y = FWHT_batch(FWHT_feat(acc)) * sx*sw/4096 + bias
    fwht_rows_i32<<<BD, 1024>>>(acc, zbuf);
    fwht64_pass<<<dim3(FD / 64, 64), 256>>>(zbuf, zbuf, FD, 64, 1,  1.0f,          nullptr, nullptr, nullptr);
    fwht64_pass<<<dim3(FD / 64, 64), 256>>>(zbuf, out,  FD, 1,  64, 1.0f / 4096.0f, mx,      nullptr, bias);
}

// round 2
// speedup vs baseline: 1.2935x; 1.2935x over previous
#include <cuda_runtime.h>
#include <cstdint>
#include <cstddef>

#define BD 4096   // batch
#define ID 2048   // in features
#define FD 4096   // out features

// ---------------------------------------------------------------------------
// Scratch (device globals; no dynamic allocation allowed)
// ---------------------------------------------------------------------------
__device__ float       g_xbuf[(size_t)BD * ID];
__device__ float       g_wbuf[(size_t)ID * FD];
__device__ float       g_zbuf[(size_t)BD * FD];
__device__ int         g_acc [(size_t)BD * FD];
__device__ signed char g_qx  [(size_t)BD * ID];
__device__ signed char g_qwT [(size_t)FD * ID];
__device__ unsigned    g_maxbits[2];

__global__ void zero_max_kernel(unsigned* m) {
    if (threadIdx.x < 2) m[threadIdx.x] = 0u;
}

// ---------------------------------------------------------------------------
// Fast 4096-pt FWHT along contiguous rows. 1024 threads, 4 elems/thread.
// Stages: 2 in-register (bits 0-1), 5 shfl (bits 2-6), smem transpose,
// 5 shfl (bits 7-11), smem transpose back to natural order for coalesced IO.
// Butterfly stages of a Walsh-Hadamard transform commute, so order is free.
// ---------------------------------------------------------------------------
__device__ __forceinline__ void load_row4(const float* p, int t, float v[4]) {
    float4 f = ((const float4*)p)[t];
    v[0] = f.x; v[1] = f.y; v[2] = f.z; v[3] = f.w;
}
__device__ __forceinline__ void load_row4(const int* p, int t, float v[4]) {
    int4 f = ((const int4*)p)[t];
    v[0] = (float)f.x; v[1] = (float)f.y; v[2] = (float)f.z; v[3] = (float)f.w;
}

template<typename Tin, bool DO_MAX>
__global__ __launch_bounds__(1024, 2)
void fwht_rows_kernel(const Tin* __restrict__ in, float* __restrict__ out,
                      float scale, unsigned* __restrict__ maxbits)
{
    __shared__ float4 s4[1024];     // 16 KB
    __shared__ float red[32];

    const int t = threadIdx.x;
    const int l = t & 31;
    const int w = t >> 5;
    const size_t row = blockIdx.x;

    float v[4];
    load_row4(in + row * 4096, t, v);

    // bits 0,1 in registers
    { float a, b;
      a = v[0]; b = v[1]; v[0] = a + b; v[1] = a - b;
      a = v[2]; b = v[3]; v[2] = a + b; v[3] = a - b;
      a = v[0]; b = v[2]; v[0] = a + b; v[2] = a - b;
      a = v[1]; b = v[3]; v[1] = a + b; v[3] = a - b; }

    // bits 2..6 via shfl (ownership r4 = t, lane = r bits 2..6)
    #pragma unroll
    for (int m = 1; m <= 16; m <<= 1) {
        #pragma unroll
        for (int j = 0; j < 4; ++j) {
            float per = __shfl_xor_sync(0xffffffffu, v[j], m);
            v[j] = (l & m) ? per - v[j] : v[j] + per;
        }
    }

    // swizzled transpose: phys(r4) = r4 ^ (r4>>5)
    s4[t ^ w] = make_float4(v[0], v[1], v[2], v[3]);
    __syncthreads();
    {
        int r4 = (l << 5) | w;       // ownership 2: lane = r bits 7..11
        float4 f = s4[r4 ^ l];
        v[0] = f.x; v[1] = f.y; v[2] = f.z; v[3] = f.w;
    }

    // bits 7..11 via shfl
    #pragma unroll
    for (int m = 1; m <= 16; m <<= 1) {
        #pragma unroll
        for (int j = 0; j < 4; ++j) {
            float per = __shfl_xor_sync(0xffffffffu, v[j], m);
            v[j] = (l & m) ? per - v[j] : v[j] + per;
        }
    }

    // back to natural order for coalesced store
    {
        int r4 = (l << 5) | w;
        s4[r4 ^ l] = make_float4(v[0], v[1], v[2], v[3]);
    }
    __syncthreads();
    float4 f = s4[t ^ w];

    float4 o = make_float4(f.x * scale, f.y * scale, f.z * scale, f.w * scale);
    ((float4*)(out + row * 4096))[t] = o;

    if (DO_MAX) {
        float lmax = fmaxf(fmaxf(fabsf(o.x), fabsf(o.y)), fmaxf(fabsf(o.z), fabsf(o.w)));
        #pragma unroll
        for (int m = 16; m; m >>= 1) lmax = fmaxf(lmax, __shfl_xor_sync(0xffffffffu, lmax, m));
        if (l == 0) red[w] = lmax;
        __syncthreads();
        if (t < 32) {
            float r2 = red[t];
            #pragma unroll
            for (int m = 16; m; m >>= 1) r2 = fmaxf(r2, __shfl_xor_sync(0xffffffffu, r2, m));
            if (t == 0) atomicMax(maxbits, __float_as_uint(r2));
        }
    }
}

// ---------------------------------------------------------------------------
// One-pass 4096-pt FWHT along dim0 of [4096, ncols]. CTA = 8 columns,
// 1024 threads, 32 elems/thread, 128 KB dynamic smem.
// Stages: 5 reg (bits 0-4) + 2 shfl (bits 5-6) + smem exchange + 5 reg (7-11).
// ---------------------------------------------------------------------------
template<bool DO_MAX, bool FINAL>
__global__ __launch_bounds__(1024)
void fwht_dim0_kernel(const float* __restrict__ in, float* __restrict__ out,
                      int ncols, float scale,
                      const unsigned* __restrict__ scalebits,
                      unsigned* __restrict__ maxbits,
                      const float* __restrict__ bias)
{
    extern __shared__ float4 sm4[];   // 8 * 1024 float4 = 128 KB
    __shared__ float red[32];

    const int t = threadIdx.x;
    const int c = t & 7;
    const int p = t >> 3;             // 0..127
    const int l = t & 31;
    const int w = t >> 5;             // == p >> 2
    const int c0 = blockIdx.x * 8;

    float v[32];

    // phase 1 ownership: rows r = (p<<5) | j
    {
        const float* ip = in + (size_t)(p << 5) * ncols + c0 + c;
        #pragma unroll
        for (int j = 0; j < 32; ++j) v[j] = ip[(size_t)j * ncols];
    }

    // bits 0..4 in registers
    #pragma unroll
    for (int st = 0; st < 5; ++st) {
        const int h = 1 << st;
        #pragma unroll
        for (int j = 0; j < 32; ++j)
            if ((j & h) == 0) {
                float a = v[j], b = v[j + h];
                v[j] = a + b; v[j + h] = a - b;
            }
    }

    // bits 5,6 via shfl (r bit5 = lane bit3, r bit6 = lane bit4)
    #pragma unroll
    for (int m = 8; m <= 16; m <<= 1) {
        #pragma unroll
        for (int j = 0; j < 32; ++j) {
            float per = __shfl_xor_sync(0xffffffffu, v[j], m);
            v[j] = (l & m) ? per - v[j] : v[j] + per;
        }
    }

    // store: float4 index q = 8p + jj, slot = (c<<10) + (q ^ c)
    #pragma unroll
    for (int jj = 0; jj < 8; ++jj) {
        int phys = (c << 10) + (((p << 3) + jj) ^ c);
        sm4[phys] = make_float4(v[4 * jj], v[4 * jj + 1], v[4 * jj + 2], v[4 * jj + 3]);
    }
    __syncthreads();

    // phase 2 ownership: rows r = (j<<7) | p   (scalar swizzled reads)
    {
        const float* smf = (const float*)sm4;
        #pragma unroll
        for (int j = 0; j < 32; ++j) {
            int q  = (j << 5) + w;                  // r >> 2
            int phys = (c << 10) + (q ^ c);
            v[j] = smf[phys * 4 + (p & 3)];
        }
    }

    // bits 7..11 in registers
    #pragma unroll
    for (int st = 0; st < 5; ++st) {
        const int h = 1 << st;
        #pragma unroll
        for (int j = 0; j < 32; ++j)
            if ((j & h) == 0) {
                float a = v[j], b = v[j + h];
                v[j] = a + b; v[j + h] = a - b;
            }
    }

    float sc = scale;
    float bv = 0.0f;
    if (FINAL) {
        float sx = __uint_as_float(scalebits[0]) / 127.0f;
        float sw = __uint_as_float(scalebits[1]) / 127.0f;
        sc *= sx * sw;
        bv = bias[c0 + c];
    }

    float lmax = 0.0f;
    {
        float* op = out + (size_t)p * ncols + c0 + c;
        #pragma unroll
        for (int j = 0; j < 32; ++j) {
            float o = v[j] * sc + bv;
            op[(size_t)(j << 7) * ncols] = o;
            if (DO_MAX) lmax = fmaxf(lmax, fabsf(o));
        }
    }

    if (DO_MAX) {
        #pragma unroll
        for (int m = 16; m; m >>= 1) lmax = fmaxf(lmax, __shfl_xor_sync(0xffffffffu, lmax, m));
        if (l == 0) red[w] = lmax;
        __syncthreads();
        if (t < 32) {
            float r2 = red[t];
            #pragma unroll
            for (int m = 16; m; m >>= 1) r2 = fmaxf(r2, __shfl_xor_sync(0xffffffffu, r2, m));
            if (t == 0) atomicMax(maxbits, __float_as_uint(r2));
        }
    }
}

// ---------------------------------------------------------------------------
// Stochastic quantization (exact same float ops as reference)
// ---------------------------------------------------------------------------
__device__ __forceinline__ int squant1(float xv, float nv, float s) {
    float xs = xv / s;
    float f  = floorf(xs);
    float qv = f + ((nv < xs - f) ? 1.0f : 0.0f);
    qv = fminf(fmaxf(qv, -127.0f), 127.0f);
    return (int)qv;
}

__global__ void quant_x_kernel(const float4* __restrict__ v, const float4* __restrict__ noise,
                               char4* __restrict__ q,
                               const unsigned* __restrict__ maxbits, int n4)
{
    const float s = __uint_as_float(*maxbits) / 127.0f;
    const int stride = gridDim.x * blockDim.x;
    for (int i = blockIdx.x * blockDim.x + threadIdx.x; i < n4; i += stride) {
        float4 x = v[i], nz = noise[i];
        q[i] = make_char4((signed char)squant1(x.x, nz.x, s),
                          (signed char)squant1(x.y, nz.y, s),
                          (signed char)squant1(x.z, nz.z, s),
                          (signed char)squant1(x.w, nz.w, s));
    }
}

// Quantize w and store TRANSPOSED: wr [K=2048, N=4096] -> qT [N=4096, K=2048].
__global__ void quant_w_T_kernel(const float* __restrict__ wr, const float* __restrict__ noise,
                                 signed char* __restrict__ qT,
                                 const unsigned* __restrict__ maxbits)
{
    __shared__ signed char tb[64][68];
    const float s = __uint_as_float(*maxbits) / 127.0f;
    const int k0 = blockIdx.x * 64;
    const int n0 = blockIdx.y * 64;
    const int tid = threadIdx.x;   // 256

    #pragma unroll
    for (int it = 0; it < 4; ++it) {
        int idx = tid + it * 256;           // 0..1023
        int kl = idx >> 4, nq = (idx & 15) * 4;
        size_t gi = (size_t)(k0 + kl) * FD + n0 + nq;
        float4 xv = *(const float4*)(wr + gi);
        float4 nv = *(const float4*)(noise + gi);
        tb[nq + 0][kl] = (signed char)squant1(xv.x, nv.x, s);
        tb[nq + 1][kl] = (signed char)squant1(xv.y, nv.y, s);
        tb[nq + 2][kl] = (signed char)squant1(xv.z, nv.z, s);
        tb[nq + 3][kl] = (signed char)squant1(xv.w, nv.w, s);
    }
    __syncthreads();

    #pragma unroll
    for (int it = 0; it < 4; ++it) {
        int idx = tid + it * 256;
        int nl = idx >> 4, k4 = (idx & 15) * 4;
        char4 vv = make_char4(tb[nl][k4], tb[nl][k4 + 1], tb[nl][k4 + 2], tb[nl][k4 + 3]);
        *(char4*)&qT[(size_t)(n0 + nl) * ID + k0 + k4] = vv;
    }
}

// ---------------------------------------------------------------------------
// int8 GEMM: C[M=4096, N=4096] (int32) = A[M,K=2048] * B[N,K]^T
// 128x128 CTA tile, K-step 64, double-buffered cp.async,
// mma.sync.aligned.m16n8k32.row.col.s32.s8.s8.s32
// ---------------------------------------------------------------------------
__device__ __forceinline__ void cp16(unsigned smem, const void* gmem) {
    asm volatile("cp.async.cg.shared.global [%0], [%1], 16;" :: "r"(smem), "l"(gmem));
}

__global__ __launch_bounds__(256, 2)
void gemm_s8_kernel(const signed char* __restrict__ A,
                    const signed char* __restrict__ B,
                    int* __restrict__ C)
{
    __shared__ __align__(16) signed char As[2][128 * 64];
    __shared__ __align__(16) signed char Bs[2][128 * 64];

    const int m0 = blockIdx.y * 128;
    const int n0 = blockIdx.x * 128;
    const int tid  = threadIdx.x;
    const int lane = tid & 31;
    const int warp = tid >> 5;
    const int wm = warp & 1;
    const int wn = warp >> 1;

    const int lr = tid >> 2;
    const int lk = (tid & 3) * 16;

    int c[4][4][4];
    #pragma unroll
    for (int i = 0; i < 4; ++i)
        #pragma unroll
        for (int j = 0; j < 4; ++j)
            #pragma unroll
            for (int k = 0; k < 4; ++k) c[i][j][k] = 0;

    auto load_tile = [&](int buf, int k0) {
        const signed char* ga = A + (size_t)(m0 + lr) * ID + k0 + lk;
        const signed char* gb = B + (size_t)(n0 + lr) * ID + k0 + lk;
        unsigned sa = (unsigned)__cvta_generic_to_shared(&As[buf][lr * 64 + lk]);
        unsigned sb = (unsigned)__cvta_generic_to_shared(&Bs[buf][lr * 64 + lk]);
        cp16(sa, ga);
        cp16(sb, gb);
        cp16(sa + 64 * 64, ga + (size_t)64 * ID);
        cp16(sb + 64 * 64, gb + (size_t)64 * ID);
    };

    load_tile(0, 0);
    asm volatile("cp.async.commit_group;");

    const int KT = ID / 64;
    for (int kt = 0; kt < KT; ++kt) {
        if (kt + 1 < KT) {
            load_tile((kt + 1) & 1, (kt + 1) * 64);
            asm volatile("cp.async.commit_group;");
            asm volatile("cp.async.wait_group 1;");
        } else {
            asm volatile("cp.async.wait_group 0;");
        }
        __syncthreads();

        const signed char* as = As[kt & 1];
        const signed char* bs = Bs[kt & 1];

        #pragma unroll
        for (int h = 0; h < 2; ++h) {
            const int kk = h * 32 + (lane & 3) * 4;
            int a[4][4], b[4][2];
            #pragma unroll
            for (int mi = 0; mi < 4; ++mi) {
                int r = wm * 64 + mi * 16 + (lane >> 2);
                a[mi][0] = *(const int*)(as + r * 64 + kk);
                a[mi][1] = *(const int*)(as + (r + 8) * 64 + kk);
                a[mi][2] = *(const int*)(as + r * 64 + kk + 16);
                a[mi][3] = *(const int*)(as + (r + 8) * 64 + kk + 16);
            }
            #pragma unroll
            for (int ni = 0; ni < 4; ++ni) {
                int cn = wn * 32 + ni * 8 + (lane >> 2);
                b[ni][0] = *(const int*)(bs + cn * 64 + kk);
                b[ni][1] = *(const int*)(bs + cn * 64 + kk + 16);
            }
            #pragma unroll
            for (int mi = 0; mi < 4; ++mi)
                #pragma unroll
                for (int ni = 0; ni < 4; ++ni)
                    asm volatile(
                        "mma.sync.aligned.m16n8k32.row.col.s32.s8.s8.s32 "
                        "{%0,%1,%2,%3},{%4,%5,%6,%7},{%8,%9},{%0,%1,%2,%3};"
                        : "+r"(c[mi][ni][0]), "+r"(c[mi][ni][1]),
                          "+r"(c[mi][ni][2]), "+r"(c[mi][ni][3])
                        : "r"(a[mi][0]), "r"(a[mi][1]), "r"(a[mi][2]), "r"(a[mi][3]),
                          "r"(b[ni][0]), "r"(b[ni][1]));
        }
        __syncthreads();
    }

    #pragma unroll
    for (int mi = 0; mi < 4; ++mi) {
        #pragma unroll
        for (int ni = 0; ni < 4; ++ni) {
            int row = m0 + wm * 64 + mi * 16 + (lane >> 2);
            int col = n0 + wn * 32 + ni * 8 + (lane & 3) * 2;
            *(int2*)&C[(size_t)row * FD + col]       = make_int2(c[mi][ni][0], c[mi][ni][1]);
            *(int2*)&C[(size_t)(row + 8) * FD + col] = make_int2(c[mi][ni][2], c[mi][ni][3]);
        }
    }
}

// ---------------------------------------------------------------------------
extern "C" void kernel_launch(void* const* d_in, const int* in_sizes, int n_in,
                              void* d_out, int out_size)
{
    const float* x    = (const float*)d_in[0];  // [4096, 2048]
    const float* w    = (const float*)d_in[1];  // [2048, 4096]
    const float* bias = (const float*)d_in[2];  // [4096]
    const float* nx   = (const float*)d_in[5];  // [4096, 2048]
    const float* nw   = (const float*)d_in[6];  // [2048, 4096]
    float* out = (float*)d_out;                 // [4096, 4096]

    float *xbuf, *wbuf, *zbuf;
    int* acc;
    signed char *qx, *qwT;
    unsigned* mx;
    cudaGetSymbolAddress((void**)&xbuf, g_xbuf);
    cudaGetSymbolAddress((void**)&wbuf, g_wbuf);
    cudaGetSymbolAddress((void**)&zbuf, g_zbuf);
    cudaGetSymbolAddress((void**)&acc,  g_acc);
    cudaGetSymbolAddress((void**)&qx,   g_qx);
    cudaGetSymbolAddress((void**)&qwT,  g_qwT);
    cudaGetSymbolAddress((void**)&mx,   g_maxbits);

    const int SMEM_D0 = 8 * 1024 * sizeof(float4);  // 128 KB
    cudaFuncSetAttribute(fwht_dim0_kernel<true, false>,
                         cudaFuncAttributeMaxDynamicSharedMemorySize, SMEM_D0);
    cudaFuncSetAttribute(fwht_dim0_kernel<false, true>,
                         cudaFuncAttributeMaxDynamicSharedMemorySize, SMEM_D0);

    zero_max_kernel<<<1, 32>>>(mx);

    // xr = FWHT_batch(x)/64 (one pass) ; max|xr| -> mx[0]
    fwht_dim0_kernel<true, false><<<ID / 8, 1024, SMEM_D0>>>(
        x, xbuf, ID, 1.0f / 64.0f, nullptr, mx + 0, nullptr);

    // wr = FWHT_feat(w)/64 ; max|wr| -> mx[1]
    fwht_rows_kernel<float, true><<<ID, 1024>>>(w, wbuf, 1.0f / 64.0f, mx + 1);

    // stochastic int8 quantization
    quant_x_kernel<<<2048, 256>>>((const float4*)xbuf, (const float4*)nx,
                                  (char4*)qx, mx + 0, (int)((size_t)BD * ID / 4));
    quant_w_T_kernel<<<dim3(ID / 64, FD / 64), 256>>>(wbuf, nw, qwT, mx + 1);

    // exact int8 GEMM
    gemm_s8_kernel<<<dim3(FD / 128, BD / 128), 256>>>(qx, qwT, acc);

    // y = FWHT_batch(FWHT_feat(acc)) * sx*sw/4096 + bias
    fwht_rows_kernel<int, false><<<BD, 1024>>>(acc, zbuf, 1.0f, nullptr);
    fwht_dim0_kernel<false, true><<<FD / 8, 1024, SMEM_D0>>>(
        zbuf, out, FD, 1.0f / 4096.0f, mx, nullptr, bias);
}